// round 13
// baseline (speedup 1.0000x reference)
#include <cuda_runtime.h>
#include <cuda_fp16.h>
#include <cstdint>
#include <math.h>

#define VOCAB 50000
#define HID   256
#define BATCH 512
#define G3H   768
#define KDIM  256

// K3: persistent, A resident (4 K-stage buffers), B ring-3, BK=64
#define BK3    64
#define NST3   (KDIM / BK3)          // 4
#define TM3    128
#define TN3    128
#define ST3_A  (TM3 * 128)           // 16 KB per A K-stage
#define ST3_B  (TN3 * 128)           // 16 KB per B stage
#define SMEM3  (4 * ST3_A + 3 * ST3_B)   // 112 KB
#define NTILES 391                    // ceil(50000/128)
#define YSTRIDE 74                    // grid.y

// K1: BK=32, ring 4, 128x64, 3 CTA/SM (R10 measured-good)
#define BK1   32
#define NST1  (KDIM / BK1)           // 8
#define TM1   128
#define TN1   64
#define ST1_A (TM1 * 64)
#define ST1_B (TN1 * 64)
#define ST1   (ST1_A + ST1_B)        // 12 KB
#define SMEM1 (4 * ST1)              // 48 KB

// scratch (static device globals -- allocation-free)
__device__ float  g_gh[BATCH * G3H];
__device__ float  g_gi[BATCH * G3H];
__device__ __half g_woh[(size_t)VOCAB * HID];
__device__ __half g_whh[G3H * HID];
__device__ __half g_hidh[BATCH * HID];
__device__ __half g_h1h[BATCH * HID];

// ---------------- helpers ----------------
__device__ __forceinline__ uint32_t smem_u32(const void* p) {
    uint32_t a;
    asm("{ .reg .u64 t; cvta.to.shared.u64 t, %1; cvt.u32.u64 %0, t; }" : "=r"(a) : "l"(p));
    return a;
}
__device__ __forceinline__ void cp16(uint32_t d, const void* g) {
    asm volatile("cp.async.cg.shared.global [%0], [%1], 16;" :: "r"(d), "l"(g));
}
__device__ __forceinline__ void ldmX4(uint32_t a[4], uint32_t addr) {
    asm volatile("ldmatrix.sync.aligned.m8n8.x4.shared.b16 {%0,%1,%2,%3}, [%4];"
                 : "=r"(a[0]), "=r"(a[1]), "=r"(a[2]), "=r"(a[3]) : "r"(addr));
}
__device__ __forceinline__ void ldmX2(uint32_t b[2], uint32_t addr) {
    asm volatile("ldmatrix.sync.aligned.m8n8.x2.shared.b16 {%0,%1}, [%2];"
                 : "=r"(b[0]), "=r"(b[1]) : "r"(addr));
}
__device__ __forceinline__ void mma16816(float c[4], unsigned a0, unsigned a1,
                                         unsigned a2, unsigned a3,
                                         unsigned b0, unsigned b1) {
    asm volatile(
        "mma.sync.aligned.m16n8k16.row.col.f32.f16.f16.f32 "
        "{%0,%1,%2,%3}, {%4,%5,%6,%7}, {%8,%9}, {%0,%1,%2,%3};\n"
        : "+f"(c[0]), "+f"(c[1]), "+f"(c[2]), "+f"(c[3])
        : "r"(a0), "r"(a1), "r"(a2), "r"(a3), "r"(b0), "r"(b1));
}
__device__ __forceinline__ float htanh(float x) {
    float y;
    asm("tanh.approx.f32 %0, %1;" : "=f"(y) : "f"(x));
    return y;
}

// ---------------- conv w_out (side stream) ----------------
__global__ __launch_bounds__(256) void convk(const float4* __restrict__ s,
                                             __half2* __restrict__ d, int n4) {
    int i = blockIdx.x * 256 + threadIdx.x;
    if (i < n4) {
        float4 v = s[i];
        d[2 * i]     = __floats2half2_rn(v.x, v.y);
        d[2 * i + 1] = __floats2half2_rn(v.z, v.w);
    }
}

// ---------------- w_ih gather (own stream) ----------------
__global__ __launch_bounds__(256) void gather_gi(
    const int* __restrict__ ids, const float* __restrict__ w_ih,
    const float* __restrict__ b_ih, float* __restrict__ gi)
{
    int idx = blockIdx.x * 256 + threadIdx.x;      // b*768 + h
    int b = idx / G3H, h = idx - b * G3H;
    int iv = __ldg(&ids[b]);
    gi[idx] = __ldg(&w_ih[(size_t)h * VOCAB + iv]) + b_ih[h];
}

// ---------------- small convs (main stream) ----------------
#define CONV1_N4 ((G3H * HID) / 4)
#define CONV2_N4 ((BATCH * HID) / 4)
__global__ __launch_bounds__(256) void convsmall(
    const float4* __restrict__ w_hh, __half2* __restrict__ whh,
    const float4* __restrict__ hid, __half2* __restrict__ hih)
{
    int i = blockIdx.x * 256 + threadIdx.x;
    if (i < CONV1_N4) {
        float4 v = w_hh[i];
        whh[2 * i]     = __floats2half2_rn(v.x, v.y);
        whh[2 * i + 1] = __floats2half2_rn(v.z, v.w);
    } else {
        int j = i - CONV1_N4;
        if (j < CONV2_N4) {
            float4 v = hid[j];
            hih[2 * j]     = __floats2half2_rn(v.x, v.y);
            hih[2 * j + 1] = __floats2half2_rn(v.z, v.w);
        }
    }
}

// ---------------- K1: gh = hih @ whh^T  (R10 exact: 128x64, BK=32, ring 4) ----
__global__ __launch_bounds__(256, 3) void gemm_k1(
    const __half* __restrict__ A, const __half* __restrict__ B,
    float* __restrict__ C)
{
    extern __shared__ char smem[];
    const int tid  = threadIdx.x;
    const int lane = tid & 31;
    const int warp = tid >> 5;
    const int wm   = warp & 3;
    const int wn   = warp >> 2;
    const int grp  = lane >> 2;
    const int kq   = lane & 3;
    const int m0   = blockIdx.x * TM1;
    const int n0   = blockIdx.y * TN1;
    const uint32_t sbase = smem_u32(smem);

    const int rcp = tid >> 2;
    const int cc  = tid & 3;

    const int aRow = wm * 32 + (lane & 15);
    const int aSw  = ((lane & 15) >> 1) & 3;
    const int aK   = lane >> 4;
    const int bRow = wn * 32 + ((lane >> 4) << 3) + (lane & 7);
    const int bSw  = ((lane & 7) >> 1) & 3;
    const int bK   = (lane >> 3) & 1;

    float acc[2][4][4];
#pragma unroll
    for (int mt = 0; mt < 2; mt++)
#pragma unroll
        for (int nt = 0; nt < 4; nt++)
#pragma unroll
            for (int i = 0; i < 4; i++) acc[mt][nt][i] = 0.f;

    auto issue = [&](int s) {
        const int buf = s & 3;
        const uint32_t sA = sbase + buf * ST1;
        const uint32_t sB = sA + ST1_A;
        const int k0 = s * BK1;
#pragma unroll
        for (int i = 0; i < 2; i++) {
            int r = rcp + i * 64;
            int swr = ((cc ^ ((r >> 1) & 3)) << 4);
            cp16(sA + r * 64 + swr, A + (size_t)(m0 + r) * KDIM + k0 + cc * 8);
        }
        {
            int sw = ((cc ^ ((rcp >> 1) & 3)) << 4);
            cp16(sB + rcp * 64 + sw, B + (size_t)(n0 + rcp) * KDIM + k0 + cc * 8);
        }
        asm volatile("cp.async.commit_group;");
    };

    issue(0); issue(1); issue(2);
    for (int s = 0; s < NST1; s++) {
        asm volatile("cp.async.wait_group %0;" :: "n"(2));
        __syncthreads();
        if (s + 3 < NST1) issue(s + 3);
        else asm volatile("cp.async.commit_group;");
        const int buf = s & 3;
        const uint32_t sA = sbase + buf * ST1;
        const uint32_t sB = sA + ST1_A;
#pragma unroll
        for (int kc = 0; kc < 2; kc++) {
            uint32_t a[2][4], b[4][2];
#pragma unroll
            for (int mt = 0; mt < 2; mt++)
                ldmX4(a[mt], sA + (aRow + mt * 16) * 64 + (((2 * kc + aK) ^ aSw) << 4));
#pragma unroll
            for (int p = 0; p < 2; p++) {
                uint32_t r4[4];
                ldmX4(r4, sB + (bRow + p * 16) * 64 + (((2 * kc + bK) ^ bSw) << 4));
                b[2 * p][0]     = r4[0]; b[2 * p][1]     = r4[1];
                b[2 * p + 1][0] = r4[2]; b[2 * p + 1][1] = r4[3];
            }
#pragma unroll
            for (int mt = 0; mt < 2; mt++)
#pragma unroll
                for (int nt = 0; nt < 4; nt++)
                    mma16816(acc[mt][nt], a[mt][0], a[mt][1], a[mt][2], a[mt][3],
                             b[nt][0], b[nt][1]);
        }
    }

#pragma unroll
    for (int mt = 0; mt < 2; mt++) {
        int row = m0 + wm * 32 + mt * 16 + grp;
#pragma unroll
        for (int nt = 0; nt < 4; nt++) {
            int col = n0 + wn * 32 + nt * 8 + 2 * kq;
            float2 v0, v1;
            v0.x = acc[mt][nt][0]; v0.y = acc[mt][nt][1];
            v1.x = acc[mt][nt][2]; v1.y = acc[mt][nt][3];
            *(float2*)(C + (size_t)row * G3H + col)       = v0;
            *(float2*)(C + (size_t)(row + 8) * G3H + col) = v1;
        }
    }
}

// ---------------- GRU combine (R10 exact) ----------------
__global__ __launch_bounds__(HID) void gru_comb(
    const float* __restrict__ gi, const float* __restrict__ gh,
    const float* __restrict__ b_hh, const float* __restrict__ h0,
    float* __restrict__ h1, __half* __restrict__ h1h)
{
    const int b = blockIdx.x;
    const int h = threadIdx.x;
    const float* gib = gi + (size_t)b * G3H;
    const float* ghb = gh + (size_t)b * G3H;

    float gh_r = ghb[h]           + b_hh[h];
    float gh_z = ghb[h + HID]     + b_hh[h + HID];
    float gh_n = ghb[h + 2 * HID] + b_hh[h + 2 * HID];

    float r = 0.5f * (1.0f + htanh(0.5f * (gib[h] + gh_r)));
    float z = 0.5f * (1.0f + htanh(0.5f * (gib[h + HID] + gh_z)));
    float n = htanh(gib[h + 2 * HID] + r * gh_n);
    float hp = h0[(size_t)b * HID + h];
    float hv = (1.0f - z) * n + z * hp;
    h1[(size_t)b * HID + h]  = hv;
    h1h[(size_t)b * HID + h] = __float2half(hv);
}

// ---------------- K3: persistent logits GEMM ----------------
// grid (4, 74): CTA (x, y) holds A slab [128x..128x+128) resident in smem and
// loops vocab tiles n0 = (y + 74t)*128. B streams through a 3-slot cp.async
// ring continuously across tiles, so next-tile prefetch overlaps the epilogue.
__global__ __launch_bounds__(256, 2) void gemm_out(
    const __half* __restrict__ A, const __half* __restrict__ B,
    const float* __restrict__ bias, float* __restrict__ C)
{
    extern __shared__ char smem[];
    const int tid  = threadIdx.x;
    const int lane = tid & 31;
    const int warp = tid >> 5;
    const int wm   = warp & 1;        // 2 warps along M
    const int wn   = warp >> 1;       // 4 warps along N
    const int grp  = lane >> 2;
    const int kq   = lane & 3;
    const int m0   = blockIdx.x * TM3;
    const uint32_t sbase = smem_u32(smem);
    const uint32_t bbase = sbase + 4 * ST3_A;

    const int rcp = tid >> 3;         // 0..31
    const int cc  = tid & 7;

    const int aRow = wm * 64 + (lane & 15);
    const int aSw  = lane & 7;
    const int aK   = lane >> 4;
    const int bRow = wn * 32 + ((lane >> 4) << 3) + (lane & 7);
    const int bSw  = lane & 7;
    const int bK   = (lane >> 3) & 1;

    const int nt = (NTILES - blockIdx.y + (YSTRIDE - 1)) / YSTRIDE;

    // ---- A prologue: all 4 K-stages loaded once (64 KB, one group) ----
#pragma unroll
    for (int s = 0; s < 4; s++) {
#pragma unroll
        for (int i = 0; i < 4; i++) {
            int r = rcp + 32 * i;
            uint32_t dst = s * ST3_A + r * 128 + ((cc ^ (r & 7)) << 4);
            cp16(sbase + dst, A + (size_t)(m0 + r) * KDIM + s * BK3 + cc * 8);
        }
    }
    asm volatile("cp.async.commit_group;");

    auto issueB = [&](int g) {
        const int t = g >> 2, s = g & 3;
        const int n0 = (blockIdx.y + t * YSTRIDE) * TN3;
        const uint32_t sB = bbase + (g % 3) * ST3_B;
        const int k0 = s * BK3;
#pragma unroll
        for (int i = 0; i < 4; i++) {
            int r = rcp + 32 * i;
            uint32_t dst = r * 128 + ((cc ^ (r & 7)) << 4);
            int rb = n0 + r;
            if (rb > VOCAB - 1) rb = VOCAB - 1;
            cp16(sB + dst, B + (size_t)rb * KDIM + k0 + cc * 8);
        }
        asm volatile("cp.async.commit_group;");
    };

    issueB(0); issueB(1);
    asm volatile("cp.async.wait_group 2;");    // A slab resident
    __syncthreads();

    float acc[4][4][4];
#pragma unroll
    for (int mt = 0; mt < 4; mt++)
#pragma unroll
        for (int nn = 0; nn < 4; nn++)
#pragma unroll
            for (int i = 0; i < 4; i++) acc[mt][nn][i] = 0.f;

    const int G = 4 * nt;
    for (int g = 0; g < G; g++) {
        asm volatile("cp.async.wait_group %0;" :: "n"(1));
        __syncthreads();
        if (g + 2 < G) issueB(g + 2);
        else asm volatile("cp.async.commit_group;");

        const uint32_t sA = sbase + (g & 3) * ST3_A;
        const uint32_t sB = bbase + (g % 3) * ST3_B;

#pragma unroll
        for (int kc = 0; kc < 4; kc++) {
            uint32_t a[4][4], b[4][2];
#pragma unroll
            for (int mt = 0; mt < 4; mt++)
                ldmX4(a[mt], sA + (aRow + mt * 16) * 128 + (((2 * kc + aK) ^ aSw) << 4));
#pragma unroll
            for (int p = 0; p < 2; p++) {
                uint32_t r4[4];
                ldmX4(r4, sB + (bRow + p * 16) * 128 + (((2 * kc + bK) ^ bSw) << 4));
                b[2 * p][0]     = r4[0]; b[2 * p][1]     = r4[1];
                b[2 * p + 1][0] = r4[2]; b[2 * p + 1][1] = r4[3];
            }
#pragma unroll
            for (int mt = 0; mt < 4; mt++)
#pragma unroll
                for (int nn = 0; nn < 4; nn++)
                    mma16816(acc[mt][nn], a[mt][0], a[mt][1], a[mt][2], a[mt][3],
                             b[nn][0], b[nn][1]);
        }

        if ((g & 3) == 3) {
            // epilogue for tile t = g >> 2 (next-tile B prefetch already in flight)
            const int n0 = (blockIdx.y + (g >> 2) * YSTRIDE) * TN3;
#pragma unroll
            for (int mt = 0; mt < 4; mt++) {
                int row = m0 + wm * 64 + mt * 16 + grp;
#pragma unroll
                for (int nn = 0; nn < 4; nn++) {
                    int col = n0 + wn * 32 + nn * 8 + 2 * kq;
                    if (col < VOCAB) {
                        float bv0 = __ldg(&bias[col]), bv1 = __ldg(&bias[col + 1]);
                        float2 v0, v1;
                        v0.x = htanh(acc[mt][nn][0] + bv0);
                        v0.y = htanh(acc[mt][nn][1] + bv1);
                        v1.x = htanh(acc[mt][nn][2] + bv0);
                        v1.y = htanh(acc[mt][nn][3] + bv1);
                        *(float2*)(C + (size_t)row * VOCAB + col)       = v0;
                        *(float2*)(C + (size_t)(row + 8) * VOCAB + col) = v1;
                    }
#pragma unroll
                    for (int i = 0; i < 4; i++) acc[mt][nn][i] = 0.f;
                }
            }
        }
    }
}

extern "C" void kernel_launch(void* const* d_in, const int* in_sizes, int n_in,
                              void* d_out, int out_size)
{
    const int*   ids    = (const int*)  d_in[0];
    const float* hidden = (const float*)d_in[1];
    const float* w_ih   = (const float*)d_in[2];
    const float* w_hh   = (const float*)d_in[3];
    const float* b_ih   = (const float*)d_in[4];
    const float* b_hh   = (const float*)d_in[5];
    const float* w_out  = (const float*)d_in[6];
    const float* b_out  = (const float*)d_in[7];

    float* out = (float*)d_out;
    float* h1  = out + ((size_t)out_size - (size_t)BATCH * HID);

    float* gh;   cudaGetSymbolAddress((void**)&gh,  g_gh);
    float* gi;   cudaGetSymbolAddress((void**)&gi,  g_gi);
    __half* woh; cudaGetSymbolAddress((void**)&woh, g_woh);
    __half* whh; cudaGetSymbolAddress((void**)&whh, g_whh);
    __half* hih; cudaGetSymbolAddress((void**)&hih, g_hidh);
    __half* h1h; cudaGetSymbolAddress((void**)&h1h, g_h1h);

    static cudaStream_t sA = nullptr, sB = nullptr;
    static cudaEvent_t ev0 = nullptr, evA = nullptr, evB = nullptr;
    if (!sA) {
        cudaFuncSetAttribute(gemm_k1,  cudaFuncAttributeMaxDynamicSharedMemorySize, SMEM1);
        cudaFuncSetAttribute(gemm_out, cudaFuncAttributeMaxDynamicSharedMemorySize, SMEM3);
        cudaStreamCreateWithFlags(&sA, cudaStreamNonBlocking);
        cudaStreamCreateWithFlags(&sB, cudaStreamNonBlocking);
        cudaEventCreateWithFlags(&ev0, cudaEventDisableTiming);
        cudaEventCreateWithFlags(&evA, cudaEventDisableTiming);
        cudaEventCreateWithFlags(&evB, cudaEventDisableTiming);
    }

    // fork
    cudaEventRecord(ev0, (cudaStream_t)0);
    cudaStreamWaitEvent(sA, ev0, 0);
    cudaStreamWaitEvent(sB, ev0, 0);

    // stream A: w_out f32 -> f16 (DRAM-roofline, hidden under pre-chain)
    {
        int n4 = (VOCAB * HID) / 4;
        convk<<<(n4 + 255) / 256, 256, 0, sA>>>((const float4*)w_out, (__half2*)woh, n4);
    }
    cudaEventRecord(evA, sA);

    // stream B: w_ih gather
    gather_gi<<<(BATCH * G3H) / 256, 256, 0, sB>>>(ids, w_ih, b_ih, gi);
    cudaEventRecord(evB, sB);

    // main: small convs -> K1
    convsmall<<<(CONV1_N4 + CONV2_N4 + 255) / 256, 256>>>(
        (const float4*)w_hh, (__half2*)whh,
        (const float4*)hidden, (__half2*)hih);
    gemm_k1<<<dim3(BATCH / TM1, G3H / TN1), 256, SMEM1>>>(hih, whh, gh);

    // join gather, combine
    cudaStreamWaitEvent((cudaStream_t)0, evB, 0);
    gru_comb<<<BATCH, HID>>>(gi, gh, b_hh, hidden, h1, h1h);

    // join conversion, persistent big GEMM
    cudaStreamWaitEvent((cudaStream_t)0, evA, 0);
    gemm_out<<<dim3(BATCH / TM3, YSTRIDE), 256, SMEM3>>>(h1h, woh, b_out, out);
}

// round 15
// speedup vs baseline: 1.0617x; 1.0617x over previous
#include <cuda_runtime.h>
#include <cuda_fp16.h>
#include <cstdint>
#include <math.h>

#define VOCAB 50000
#define HID   256
#define BATCH 512
#define G3H   768
#define KDIM  256

// K3: BK=64, ring 3, 128x128 (R10 measured-best)
#define BK3   64
#define NST3  (KDIM / BK3)           // 4
#define TM3   128
#define TN3   128
#define ST3_A (TM3 * 128)            // 16 KB
#define ST3_B (TN3 * 128)            // 16 KB
#define ST3   (ST3_A + ST3_B)        // 32 KB
#define SMEM3 (3 * ST3)              // 96 KB

// K1: BK=32, ring 4, 128x64, 3 CTA/SM (R10 measured-good)
#define BK1   32
#define NST1  (KDIM / BK1)           // 8
#define TM1   128
#define TN1   64
#define ST1_A (TM1 * 64)
#define ST1_B (TN1 * 64)
#define ST1   (ST1_A + ST1_B)        // 12 KB
#define SMEM1 (4 * ST1)              // 48 KB

// scratch (static device globals -- allocation-free)
__device__ float  g_gh[BATCH * G3H];
__device__ float  g_gi[BATCH * G3H];
__device__ __half g_woh[(size_t)VOCAB * HID];
__device__ __half g_whh[G3H * HID];
__device__ __half g_hidh[BATCH * HID];
__device__ __half g_h1h[BATCH * HID];

// ---------------- helpers ----------------
__device__ __forceinline__ uint32_t smem_u32(const void* p) {
    uint32_t a;
    asm("{ .reg .u64 t; cvta.to.shared.u64 t, %1; cvt.u32.u64 %0, t; }" : "=r"(a) : "l"(p));
    return a;
}
__device__ __forceinline__ void cp16(uint32_t d, const void* g) {
    asm volatile("cp.async.cg.shared.global [%0], [%1], 16;" :: "r"(d), "l"(g));
}
__device__ __forceinline__ void ldmX4(uint32_t a[4], uint32_t addr) {
    asm volatile("ldmatrix.sync.aligned.m8n8.x4.shared.b16 {%0,%1,%2,%3}, [%4];"
                 : "=r"(a[0]), "=r"(a[1]), "=r"(a[2]), "=r"(a[3]) : "r"(addr));
}
__device__ __forceinline__ void mma16816(float c[4], unsigned a0, unsigned a1,
                                         unsigned a2, unsigned a3,
                                         unsigned b0, unsigned b1) {
    asm volatile(
        "mma.sync.aligned.m16n8k16.row.col.f32.f16.f16.f32 "
        "{%0,%1,%2,%3}, {%4,%5,%6,%7}, {%8,%9}, {%0,%1,%2,%3};\n"
        : "+f"(c[0]), "+f"(c[1]), "+f"(c[2]), "+f"(c[3])
        : "r"(a0), "r"(a1), "r"(a2), "r"(a3), "r"(b0), "r"(b1));
}
__device__ __forceinline__ float htanh(float x) {
    float y;
    asm("tanh.approx.f32 %0, %1;" : "=f"(y) : "f"(x));
    return y;
}

// ---------------- conv w_out (side stream; hidden under pre-chain) ----------
__global__ __launch_bounds__(256) void convk(const float4* __restrict__ s,
                                             __half2* __restrict__ d, int n4) {
    int i = blockIdx.x * 256 + threadIdx.x;
    if (i < n4) {
        float4 v = s[i];
        d[2 * i]     = __floats2half2_rn(v.x, v.y);
        d[2 * i + 1] = __floats2half2_rn(v.z, v.w);
    }
}

// ---------------- fused gather + small convs (one node, main stream) --------
#define GATHER_BLOCKS ((BATCH * G3H) / 256)                 // 1536
#define CONV1_N4      ((G3H * HID) / 4)                     // 49152
#define CONV2_N4      ((BATCH * HID) / 4)                   // 32768
#define CONV_BLOCKS   ((CONV1_N4 + CONV2_N4) / 256)         // 320
#define GC_BLOCKS     (GATHER_BLOCKS + CONV_BLOCKS)

__global__ __launch_bounds__(256) void gatherconv(
    const int* __restrict__ ids, const float* __restrict__ w_ih,
    const float* __restrict__ b_ih, float* __restrict__ gi,
    const float4* __restrict__ w_hh, __half2* __restrict__ whh,
    const float4* __restrict__ hid, __half2* __restrict__ hih)
{
    int bid = blockIdx.x;
    if (bid < GATHER_BLOCKS) {
        int idx = bid * 256 + threadIdx.x;          // b*768 + h
        int b = idx / G3H, h = idx - b * G3H;
        int iv = __ldg(&ids[b]);
        gi[idx] = __ldg(&w_ih[(size_t)h * VOCAB + iv]) + b_ih[h];
    } else {
        int i = (bid - GATHER_BLOCKS) * 256 + threadIdx.x;
        if (i < CONV1_N4) {
            float4 v = w_hh[i];
            whh[2 * i]     = __floats2half2_rn(v.x, v.y);
            whh[2 * i + 1] = __floats2half2_rn(v.z, v.w);
        } else {
            int j = i - CONV1_N4;
            float4 v = hid[j];
            hih[2 * j]     = __floats2half2_rn(v.x, v.y);
            hih[2 * j + 1] = __floats2half2_rn(v.z, v.w);
        }
    }
}

// ---------------- K1: gh = hih @ whh^T  (R10 exact) ----------------
__global__ __launch_bounds__(256, 3) void gemm_k1(
    const __half* __restrict__ A, const __half* __restrict__ B,
    float* __restrict__ C)
{
    extern __shared__ char smem[];
    const int tid  = threadIdx.x;
    const int lane = tid & 31;
    const int warp = tid >> 5;
    const int wm   = warp & 3;
    const int wn   = warp >> 2;
    const int grp  = lane >> 2;
    const int kq   = lane & 3;
    const int m0   = blockIdx.x * TM1;
    const int n0   = blockIdx.y * TN1;
    const uint32_t sbase = smem_u32(smem);

    const int rcp = tid >> 2;
    const int cc  = tid & 3;

    const int aRow = wm * 32 + (lane & 15);
    const int aSw  = ((lane & 15) >> 1) & 3;
    const int aK   = lane >> 4;
    const int bRow = wn * 32 + ((lane >> 4) << 3) + (lane & 7);
    const int bSw  = ((lane & 7) >> 1) & 3;
    const int bK   = (lane >> 3) & 1;

    float acc[2][4][4];
#pragma unroll
    for (int mt = 0; mt < 2; mt++)
#pragma unroll
        for (int nt = 0; nt < 4; nt++)
#pragma unroll
            for (int i = 0; i < 4; i++) acc[mt][nt][i] = 0.f;

    auto issue = [&](int s) {
        const int buf = s & 3;
        const uint32_t sA = sbase + buf * ST1;
        const uint32_t sB = sA + ST1_A;
        const int k0 = s * BK1;
#pragma unroll
        for (int i = 0; i < 2; i++) {
            int r = rcp + i * 64;
            int swr = ((cc ^ ((r >> 1) & 3)) << 4);
            cp16(sA + r * 64 + swr, A + (size_t)(m0 + r) * KDIM + k0 + cc * 8);
        }
        {
            int sw = ((cc ^ ((rcp >> 1) & 3)) << 4);
            cp16(sB + rcp * 64 + sw, B + (size_t)(n0 + rcp) * KDIM + k0 + cc * 8);
        }
        asm volatile("cp.async.commit_group;");
    };

    issue(0); issue(1); issue(2);
    for (int s = 0; s < NST1; s++) {
        asm volatile("cp.async.wait_group %0;" :: "n"(2));
        __syncthreads();
        if (s + 3 < NST1) issue(s + 3);
        else asm volatile("cp.async.commit_group;");
        const int buf = s & 3;
        const uint32_t sA = sbase + buf * ST1;
        const uint32_t sB = sA + ST1_A;
#pragma unroll
        for (int kc = 0; kc < 2; kc++) {
            uint32_t a[2][4], b[4][2];
#pragma unroll
            for (int mt = 0; mt < 2; mt++)
                ldmX4(a[mt], sA + (aRow + mt * 16) * 64 + (((2 * kc + aK) ^ aSw) << 4));
#pragma unroll
            for (int p = 0; p < 2; p++) {
                uint32_t r4[4];
                ldmX4(r4, sB + (bRow + p * 16) * 64 + (((2 * kc + bK) ^ bSw) << 4));
                b[2 * p][0]     = r4[0]; b[2 * p][1]     = r4[1];
                b[2 * p + 1][0] = r4[2]; b[2 * p + 1][1] = r4[3];
            }
#pragma unroll
            for (int mt = 0; mt < 2; mt++)
#pragma unroll
                for (int nt = 0; nt < 4; nt++)
                    mma16816(acc[mt][nt], a[mt][0], a[mt][1], a[mt][2], a[mt][3],
                             b[nt][0], b[nt][1]);
        }
    }

#pragma unroll
    for (int mt = 0; mt < 2; mt++) {
        int row = m0 + wm * 32 + mt * 16 + grp;
#pragma unroll
        for (int nt = 0; nt < 4; nt++) {
            int col = n0 + wn * 32 + nt * 8 + 2 * kq;
            float2 v0, v1;
            v0.x = acc[mt][nt][0]; v0.y = acc[mt][nt][1];
            v1.x = acc[mt][nt][2]; v1.y = acc[mt][nt][3];
            *(float2*)(C + (size_t)row * G3H + col)       = v0;
            *(float2*)(C + (size_t)(row + 8) * G3H + col) = v1;
        }
    }
}

// ---------------- GRU combine (R10 exact) ----------------
__global__ __launch_bounds__(HID) void gru_comb(
    const float* __restrict__ gi, const float* __restrict__ gh,
    const float* __restrict__ b_hh, const float* __restrict__ h0,
    float* __restrict__ h1, __half* __restrict__ h1h)
{
    const int b = blockIdx.x;
    const int h = threadIdx.x;
    const float* gib = gi + (size_t)b * G3H;
    const float* ghb = gh + (size_t)b * G3H;

    float gh_r = ghb[h]           + b_hh[h];
    float gh_z = ghb[h + HID]     + b_hh[h + HID];
    float gh_n = ghb[h + 2 * HID] + b_hh[h + 2 * HID];

    float r = 0.5f * (1.0f + htanh(0.5f * (gib[h] + gh_r)));
    float z = 0.5f * (1.0f + htanh(0.5f * (gib[h + HID] + gh_z)));
    float n = htanh(gib[h + 2 * HID] + r * gh_n);
    float hp = h0[(size_t)b * HID + h];
    float hv = (1.0f - z) * n + z * hp;
    h1[(size_t)b * HID + h]  = hv;
    h1h[(size_t)b * HID + h] = __float2half(hv);
}

// ---------------- K3: logits = tanh(h1 @ w_out^T + b_out)  (R10 exact) ----
__global__ __launch_bounds__(256, 2) void gemm_out(
    const __half* __restrict__ A, const __half* __restrict__ B,
    const float* __restrict__ bias, float* __restrict__ C)
{
    extern __shared__ char smem[];
    const int tid  = threadIdx.x;
    const int lane = tid & 31;
    const int warp = tid >> 5;
    const int wm   = warp & 1;        // 2 warps along M (64 rows each)
    const int wn   = warp >> 1;       // 4 warps along N (32 cols each)
    const int grp  = lane >> 2;
    const int kq   = lane & 3;
    const int m0   = blockIdx.x * TM3;
    const int n0   = blockIdx.y * TN3;
    const uint32_t sbase = smem_u32(smem);

    const int rcp = tid >> 3;         // 0..31
    const int cc  = tid & 7;

    const int aRow = wm * 64 + (lane & 15);
    const int aSw  = lane & 7;
    const int aK   = lane >> 4;
    const int bRow = wn * 32 + ((lane >> 4) << 3) + (lane & 7);
    const int bSw  = lane & 7;
    const int bK   = (lane >> 3) & 1;

    float acc[4][4][4];
#pragma unroll
    for (int mt = 0; mt < 4; mt++)
#pragma unroll
        for (int nt = 0; nt < 4; nt++)
#pragma unroll
            for (int i = 0; i < 4; i++) acc[mt][nt][i] = 0.f;

    auto issue = [&](int s) {
        const int buf = s % 3;
        const uint32_t sA = sbase + buf * ST3;
        const uint32_t sB = sA + ST3_A;
        const int k0 = s * BK3;
#pragma unroll
        for (int i = 0; i < 4; i++) {           // A: 128 rows
            int r = rcp + 32 * i;
            uint32_t dst = r * 128 + ((cc ^ (r & 7)) << 4);
            cp16(sA + dst, A + (size_t)(m0 + r) * KDIM + k0 + cc * 8);
        }
#pragma unroll
        for (int i = 0; i < 4; i++) {           // B: 128 rows (clamped)
            int r = rcp + 32 * i;
            uint32_t dst = r * 128 + ((cc ^ (r & 7)) << 4);
            int rb = n0 + r;
            if (rb > VOCAB - 1) rb = VOCAB - 1;
            cp16(sB + dst, B + (size_t)rb * KDIM + k0 + cc * 8);
        }
        asm volatile("cp.async.commit_group;");
    };

    issue(0); issue(1);
    for (int s = 0; s < NST3; s++) {
        asm volatile("cp.async.wait_group %0;" :: "n"(1));
        __syncthreads();
        if (s + 2 < NST3) issue(s + 2);
        else asm volatile("cp.async.commit_group;");
        const uint32_t sA = sbase + (s % 3) * ST3;
        const uint32_t sB = sA + ST3_A;
#pragma unroll
        for (int kc = 0; kc < 4; kc++) {
            uint32_t a[4][4], b[4][2];
#pragma unroll
            for (int mt = 0; mt < 4; mt++)
                ldmX4(a[mt], sA + (aRow + mt * 16) * 128 + (((2 * kc + aK) ^ aSw) << 4));
#pragma unroll
            for (int p = 0; p < 2; p++) {
                uint32_t r4[4];
                ldmX4(r4, sB + (bRow + p * 16) * 128 + (((2 * kc + bK) ^ bSw) << 4));
                b[2 * p][0]     = r4[0]; b[2 * p][1]     = r4[1];
                b[2 * p + 1][0] = r4[2]; b[2 * p + 1][1] = r4[3];
            }
#pragma unroll
            for (int mt = 0; mt < 4; mt++)
#pragma unroll
                for (int nt = 0; nt < 4; nt++)
                    mma16816(acc[mt][nt], a[mt][0], a[mt][1], a[mt][2], a[mt][3],
                             b[nt][0], b[nt][1]);
        }
    }

#pragma unroll
    for (int mt = 0; mt < 4; mt++) {
        int row = m0 + wm * 64 + mt * 16 + grp;
#pragma unroll
        for (int nt = 0; nt < 4; nt++) {
            int col = n0 + wn * 32 + nt * 8 + 2 * kq;
            if (col < VOCAB) {
                float bv0 = bias[col], bv1 = bias[col + 1];
                float2 v0, v1;
                v0.x = htanh(acc[mt][nt][0] + bv0);
                v0.y = htanh(acc[mt][nt][1] + bv1);
                v1.x = htanh(acc[mt][nt][2] + bv0);
                v1.y = htanh(acc[mt][nt][3] + bv1);
                *(float2*)(C + (size_t)row * VOCAB + col)       = v0;
                *(float2*)(C + (size_t)(row + 8) * VOCAB + col) = v1;
            }
        }
    }
}

extern "C" void kernel_launch(void* const* d_in, const int* in_sizes, int n_in,
                              void* d_out, int out_size)
{
    const int*   ids    = (const int*)  d_in[0];
    const float* hidden = (const float*)d_in[1];
    const float* w_ih   = (const float*)d_in[2];
    const float* w_hh   = (const float*)d_in[3];
    const float* b_ih   = (const float*)d_in[4];
    const float* b_hh   = (const float*)d_in[5];
    const float* w_out  = (const float*)d_in[6];
    const float* b_out  = (const float*)d_in[7];

    float* out = (float*)d_out;
    float* h1  = out + ((size_t)out_size - (size_t)BATCH * HID);

    float* gh;   cudaGetSymbolAddress((void**)&gh,  g_gh);
    float* gi;   cudaGetSymbolAddress((void**)&gi,  g_gi);
    __half* woh; cudaGetSymbolAddress((void**)&woh, g_woh);
    __half* whh; cudaGetSymbolAddress((void**)&whh, g_whh);
    __half* hih; cudaGetSymbolAddress((void**)&hih, g_hidh);
    __half* h1h; cudaGetSymbolAddress((void**)&h1h, g_h1h);

    static cudaStream_t sA = nullptr;
    static cudaEvent_t ev0 = nullptr, evA = nullptr;
    if (!sA) {
        cudaFuncSetAttribute(gemm_k1,  cudaFuncAttributeMaxDynamicSharedMemorySize, SMEM1);
        cudaFuncSetAttribute(gemm_out, cudaFuncAttributeMaxDynamicSharedMemorySize, SMEM3);
        cudaStreamCreateWithFlags(&sA, cudaStreamNonBlocking);
        cudaEventCreateWithFlags(&ev0, cudaEventDisableTiming);
        cudaEventCreateWithFlags(&evA, cudaEventDisableTiming);
    }

    // fork: w_out f32 -> f16 on side stream (hidden under pre-chain)
    cudaEventRecord(ev0, (cudaStream_t)0);
    cudaStreamWaitEvent(sA, ev0, 0);
    {
        int n4 = (VOCAB * HID) / 4;
        convk<<<(n4 + 255) / 256, 256, 0, sA>>>((const float4*)w_out, (__half2*)woh, n4);
    }
    cudaEventRecord(evA, sA);

    // main: fused gather + small convs -> K1 -> combine
    gatherconv<<<GC_BLOCKS, 256>>>(ids, w_ih, b_ih, gi,
                                   (const float4*)w_hh, (__half2*)whh,
                                   (const float4*)hidden, (__half2*)hih);
    gemm_k1<<<dim3(BATCH / TM1, G3H / TN1), 256, SMEM1>>>(hih, whh, gh);
    gru_comb<<<BATCH, HID>>>(gi, gh, b_hh, hidden, h1, h1h);

    // join conversion, big GEMM
    cudaStreamWaitEvent((cudaStream_t)0, evA, 0);
    gemm_out<<<dim3(BATCH / TM3, (VOCAB + TN3 - 1) / TN3), 256, SMEM3>>>(
        h1h, woh, b_out, out);
}

// round 17
// speedup vs baseline: 1.1025x; 1.0384x over previous
#include <cuda_runtime.h>
#include <cuda_fp16.h>
#include <cstdint>
#include <math.h>

#define VOCAB 50000
#define HID   256
#define BATCH 512
#define G3H   768
#define KDIM  256

// K3: resident A (4 static K-stage buffers) + B ring-3, BK=64, 128x128
#define BK3   64
#define NST3  (KDIM / BK3)           // 4
#define TM3   128
#define TN3   128
#define ST3_A (TM3 * 128)            // 16 KB per A K-stage
#define ST3_B (TN3 * 128)            // 16 KB per B stage
#define SMEM3 (4 * ST3_A + 3 * ST3_B)   // 112 KB
#define GRIDY3 ((VOCAB + TN3 - 1) / TN3) // 391

// K1: BK=32, ring 4, 128x64, 3 CTA/SM (R10 measured-good)
#define BK1   32
#define NST1  (KDIM / BK1)           // 8
#define TM1   128
#define TN1   64
#define ST1_A (TM1 * 64)
#define ST1_B (TN1 * 64)
#define ST1   (ST1_A + ST1_B)        // 12 KB
#define SMEM1 (4 * ST1)              // 48 KB

// scratch (static device globals -- allocation-free)
__device__ float  g_gh[BATCH * G3H];
__device__ float  g_gi[BATCH * G3H];
__device__ __half g_woh[(size_t)VOCAB * HID];
__device__ __half g_whh[G3H * HID];
__device__ __half g_hidh[BATCH * HID];
__device__ __half g_h1h[BATCH * HID];

// ---------------- helpers ----------------
__device__ __forceinline__ uint32_t smem_u32(const void* p) {
    uint32_t a;
    asm("{ .reg .u64 t; cvta.to.shared.u64 t, %1; cvt.u32.u64 %0, t; }" : "=r"(a) : "l"(p));
    return a;
}
__device__ __forceinline__ void cp16(uint32_t d, const void* g) {
    asm volatile("cp.async.cg.shared.global [%0], [%1], 16;" :: "r"(d), "l"(g));
}
__device__ __forceinline__ void ldmX4(uint32_t a[4], uint32_t addr) {
    asm volatile("ldmatrix.sync.aligned.m8n8.x4.shared.b16 {%0,%1,%2,%3}, [%4];"
                 : "=r"(a[0]), "=r"(a[1]), "=r"(a[2]), "=r"(a[3]) : "r"(addr));
}
__device__ __forceinline__ void mma16816(float c[4], unsigned a0, unsigned a1,
                                         unsigned a2, unsigned a3,
                                         unsigned b0, unsigned b1) {
    asm volatile(
        "mma.sync.aligned.m16n8k16.row.col.f32.f16.f16.f32 "
        "{%0,%1,%2,%3}, {%4,%5,%6,%7}, {%8,%9}, {%0,%1,%2,%3};\n"
        : "+f"(c[0]), "+f"(c[1]), "+f"(c[2]), "+f"(c[3])
        : "r"(a0), "r"(a1), "r"(a2), "r"(a3), "r"(b0), "r"(b1));
}
__device__ __forceinline__ float htanh(float x) {
    float y;
    asm("tanh.approx.f32 %0, %1;" : "=f"(y) : "f"(x));
    return y;
}

// ---------------- conv w_out (side stream A; hidden under pre-chain) --------
__global__ __launch_bounds__(256) void convk(const float4* __restrict__ s,
                                             __half2* __restrict__ d, int n4) {
    int i = blockIdx.x * 256 + threadIdx.x;
    if (i < n4) {
        float4 v = s[i];
        d[2 * i]     = __floats2half2_rn(v.x, v.y);
        d[2 * i + 1] = __floats2half2_rn(v.z, v.w);
    }
}

// ---------------- w_ih gather (side stream B) ----------------
__global__ __launch_bounds__(256) void gather_gi(
    const int* __restrict__ ids, const float* __restrict__ w_ih,
    const float* __restrict__ b_ih, float* __restrict__ gi)
{
    int idx = blockIdx.x * 256 + threadIdx.x;      // b*768 + h
    int b = idx / G3H, h = idx - b * G3H;
    int iv = __ldg(&ids[b]);
    gi[idx] = __ldg(&w_ih[(size_t)h * VOCAB + iv]) + b_ih[h];
}

// ---------------- small convs (main stream) ----------------
#define CONV1_N4 ((G3H * HID) / 4)
#define CONV2_N4 ((BATCH * HID) / 4)
__global__ __launch_bounds__(256) void convsmall(
    const float4* __restrict__ w_hh, __half2* __restrict__ whh,
    const float4* __restrict__ hid, __half2* __restrict__ hih)
{
    int i = blockIdx.x * 256 + threadIdx.x;
    if (i < CONV1_N4) {
        float4 v = w_hh[i];
        whh[2 * i]     = __floats2half2_rn(v.x, v.y);
        whh[2 * i + 1] = __floats2half2_rn(v.z, v.w);
    } else {
        int j = i - CONV1_N4;
        if (j < CONV2_N4) {
            float4 v = hid[j];
            hih[2 * j]     = __floats2half2_rn(v.x, v.y);
            hih[2 * j + 1] = __floats2half2_rn(v.z, v.w);
        }
    }
}

// ---------------- K1: gh = hih @ whh^T  (R10 exact) ----------------
__global__ __launch_bounds__(256, 3) void gemm_k1(
    const __half* __restrict__ A, const __half* __restrict__ B,
    float* __restrict__ C)
{
    extern __shared__ char smem[];
    const int tid  = threadIdx.x;
    const int lane = tid & 31;
    const int warp = tid >> 5;
    const int wm   = warp & 3;
    const int wn   = warp >> 2;
    const int grp  = lane >> 2;
    const int kq   = lane & 3;
    const int m0   = blockIdx.x * TM1;
    const int n0   = blockIdx.y * TN1;
    const uint32_t sbase = smem_u32(smem);

    const int rcp = tid >> 2;
    const int cc  = tid & 3;

    const int aRow = wm * 32 + (lane & 15);
    const int aSw  = ((lane & 15) >> 1) & 3;
    const int aK   = lane >> 4;
    const int bRow = wn * 32 + ((lane >> 4) << 3) + (lane & 7);
    const int bSw  = ((lane & 7) >> 1) & 3;
    const int bK   = (lane >> 3) & 1;

    float acc[2][4][4];
#pragma unroll
    for (int mt = 0; mt < 2; mt++)
#pragma unroll
        for (int nt = 0; nt < 4; nt++)
#pragma unroll
            for (int i = 0; i < 4; i++) acc[mt][nt][i] = 0.f;

    auto issue = [&](int s) {
        const int buf = s & 3;
        const uint32_t sA = sbase + buf * ST1;
        const uint32_t sB = sA + ST1_A;
        const int k0 = s * BK1;
#pragma unroll
        for (int i = 0; i < 2; i++) {
            int r = rcp + i * 64;
            int swr = ((cc ^ ((r >> 1) & 3)) << 4);
            cp16(sA + r * 64 + swr, A + (size_t)(m0 + r) * KDIM + k0 + cc * 8);
        }
        {
            int sw = ((cc ^ ((rcp >> 1) & 3)) << 4);
            cp16(sB + rcp * 64 + sw, B + (size_t)(n0 + rcp) * KDIM + k0 + cc * 8);
        }
        asm volatile("cp.async.commit_group;");
    };

    issue(0); issue(1); issue(2);
    for (int s = 0; s < NST1; s++) {
        asm volatile("cp.async.wait_group %0;" :: "n"(2));
        __syncthreads();
        if (s + 3 < NST1) issue(s + 3);
        else asm volatile("cp.async.commit_group;");
        const int buf = s & 3;
        const uint32_t sA = sbase + buf * ST1;
        const uint32_t sB = sA + ST1_A;
#pragma unroll
        for (int kc = 0; kc < 2; kc++) {
            uint32_t a[2][4], b[4][2];
#pragma unroll
            for (int mt = 0; mt < 2; mt++)
                ldmX4(a[mt], sA + (aRow + mt * 16) * 64 + (((2 * kc + aK) ^ aSw) << 4));
#pragma unroll
            for (int p = 0; p < 2; p++) {
                uint32_t r4[4];
                ldmX4(r4, sB + (bRow + p * 16) * 64 + (((2 * kc + bK) ^ bSw) << 4));
                b[2 * p][0]     = r4[0]; b[2 * p][1]     = r4[1];
                b[2 * p + 1][0] = r4[2]; b[2 * p + 1][1] = r4[3];
            }
#pragma unroll
            for (int mt = 0; mt < 2; mt++)
#pragma unroll
                for (int nt = 0; nt < 4; nt++)
                    mma16816(acc[mt][nt], a[mt][0], a[mt][1], a[mt][2], a[mt][3],
                             b[nt][0], b[nt][1]);
        }
    }

#pragma unroll
    for (int mt = 0; mt < 2; mt++) {
        int row = m0 + wm * 32 + mt * 16 + grp;
#pragma unroll
        for (int nt = 0; nt < 4; nt++) {
            int col = n0 + wn * 32 + nt * 8 + 2 * kq;
            float2 v0, v1;
            v0.x = acc[mt][nt][0]; v0.y = acc[mt][nt][1];
            v1.x = acc[mt][nt][2]; v1.y = acc[mt][nt][3];
            *(float2*)(C + (size_t)row * G3H + col)       = v0;
            *(float2*)(C + (size_t)(row + 8) * G3H + col) = v1;
        }
    }
}

// ---------------- GRU combine (R10 exact) ----------------
__global__ __launch_bounds__(HID) void gru_comb(
    const float* __restrict__ gi, const float* __restrict__ gh,
    const float* __restrict__ b_hh, const float* __restrict__ h0,
    float* __restrict__ h1, __half* __restrict__ h1h)
{
    const int b = blockIdx.x;
    const int h = threadIdx.x;
    const float* gib = gi + (size_t)b * G3H;
    const float* ghb = gh + (size_t)b * G3H;

    float gh_r = ghb[h]           + b_hh[h];
    float gh_z = ghb[h + HID]     + b_hh[h + HID];
    float gh_n = ghb[h + 2 * HID] + b_hh[h + 2 * HID];

    float r = 0.5f * (1.0f + htanh(0.5f * (gib[h] + gh_r)));
    float z = 0.5f * (1.0f + htanh(0.5f * (gib[h + HID] + gh_z)));
    float n = htanh(gib[h + 2 * HID] + r * gh_n);
    float hp = h0[(size_t)b * HID + h];
    float hv = (1.0f - z) * n + z * hp;
    h1[(size_t)b * HID + h]  = hv;
    h1h[(size_t)b * HID + h] = __float2half(hv);
}

// ---------------- K3: logits = tanh(h1 @ w_out^T + b_out) ----------------
// Resident-A variant: the CTA's full A slab (128 x 256 f16 = 64 KB, 4 K-stage
// buffers) is loaded once in the prologue; the mainloop streams only B through
// a 3-slot cp.async ring. Halves steady-state async L1 traffic vs R10.
__global__ __launch_bounds__(256, 2) void gemm_out(
    const __half* __restrict__ A, const __half* __restrict__ B,
    const float* __restrict__ bias, float* __restrict__ C)
{
    extern __shared__ char smem[];
    const int tid  = threadIdx.x;
    const int lane = tid & 31;
    const int warp = tid >> 5;
    const int wm   = warp & 1;        // 2 warps along M (64 rows each)
    const int wn   = warp >> 1;       // 4 warps along N (32 cols each)
    const int grp  = lane >> 2;
    const int kq   = lane & 3;
    const int m0   = blockIdx.x * TM3;
    const int n0   = blockIdx.y * TN3;
    const uint32_t sbase = smem_u32(smem);
    const uint32_t bbase = sbase + 4 * ST3_A;

    const int rcp = tid >> 3;         // 0..31
    const int cc  = tid & 7;

    const int aRow = wm * 64 + (lane & 15);
    const int aSw  = lane & 7;
    const int aK   = lane >> 4;
    const int bRow = wn * 32 + ((lane >> 4) << 3) + (lane & 7);
    const int bSw  = lane & 7;
    const int bK   = (lane >> 3) & 1;

    // ---- prologue: full A slab (all 4 K-stages), one commit group ----
#pragma unroll
    for (int s = 0; s < 4; s++) {
#pragma unroll
        for (int i = 0; i < 4; i++) {
            int r = rcp + 32 * i;
            uint32_t dst = s * ST3_A + r * 128 + ((cc ^ (r & 7)) << 4);
            cp16(sbase + dst, A + (size_t)(m0 + r) * KDIM + s * BK3 + cc * 8);
        }
    }
    asm volatile("cp.async.commit_group;");

    auto issueB = [&](int s) {
        const uint32_t sB = bbase + (s % 3) * ST3_B;
        const int k0 = s * BK3;
#pragma unroll
        for (int i = 0; i < 4; i++) {
            int r = rcp + 32 * i;
            uint32_t dst = r * 128 + ((cc ^ (r & 7)) << 4);
            int rb = n0 + r;
            if (rb > VOCAB - 1) rb = VOCAB - 1;
            cp16(sB + dst, B + (size_t)rb * KDIM + k0 + cc * 8);
        }
        asm volatile("cp.async.commit_group;");
    };

    issueB(0); issueB(1);

    float acc[4][4][4];
#pragma unroll
    for (int mt = 0; mt < 4; mt++)
#pragma unroll
        for (int nt = 0; nt < 4; nt++)
#pragma unroll
            for (int i = 0; i < 4; i++) acc[mt][nt][i] = 0.f;

    for (int s = 0; s < NST3; s++) {
        // pending before wait: {B_{s+1}, B_{s+2}} (+A,B_s at s=0) -> wait to 1
        asm volatile("cp.async.wait_group %0;" :: "n"(1));
        __syncthreads();
        if (s + 2 < NST3) issueB(s + 2);
        else asm volatile("cp.async.commit_group;");

        const uint32_t sA = sbase + s * ST3_A;
        const uint32_t sB = bbase + (s % 3) * ST3_B;

#pragma unroll
        for (int kc = 0; kc < 4; kc++) {
            uint32_t a[4][4], b[4][2];
#pragma unroll
            for (int mt = 0; mt < 4; mt++)
                ldmX4(a[mt], sA + (aRow + mt * 16) * 128 + (((2 * kc + aK) ^ aSw) << 4));
#pragma unroll
            for (int p = 0; p < 2; p++) {
                uint32_t r4[4];
                ldmX4(r4, sB + (bRow + p * 16) * 128 + (((2 * kc + bK) ^ bSw) << 4));
                b[2 * p][0]     = r4[0]; b[2 * p][1]     = r4[1];
                b[2 * p + 1][0] = r4[2]; b[2 * p + 1][1] = r4[3];
            }
#pragma unroll
            for (int mt = 0; mt < 4; mt++)
#pragma unroll
                for (int nt = 0; nt < 4; nt++)
                    mma16816(acc[mt][nt], a[mt][0], a[mt][1], a[mt][2], a[mt][3],
                             b[nt][0], b[nt][1]);
        }
    }

#pragma unroll
    for (int mt = 0; mt < 4; mt++) {
        int row = m0 + wm * 64 + mt * 16 + grp;
#pragma unroll
        for (int nt = 0; nt < 4; nt++) {
            int col = n0 + wn * 32 + nt * 8 + 2 * kq;
            if (col < VOCAB) {
                float bv0 = __ldg(&bias[col]), bv1 = __ldg(&bias[col + 1]);
                float2 v0, v1;
                v0.x = htanh(acc[mt][nt][0] + bv0);
                v0.y = htanh(acc[mt][nt][1] + bv1);
                v1.x = htanh(acc[mt][nt][2] + bv0);
                v1.y = htanh(acc[mt][nt][3] + bv1);
                *(float2*)(C + (size_t)row * VOCAB + col)       = v0;
                *(float2*)(C + (size_t)(row + 8) * VOCAB + col) = v1;
            }
        }
    }
}

extern "C" void kernel_launch(void* const* d_in, const int* in_sizes, int n_in,
                              void* d_out, int out_size)
{
    const int*   ids    = (const int*)  d_in[0];
    const float* hidden = (const float*)d_in[1];
    const float* w_ih   = (const float*)d_in[2];
    const float* w_hh   = (const float*)d_in[3];
    const float* b_ih   = (const float*)d_in[4];
    const float* b_hh   = (const float*)d_in[5];
    const float* w_out  = (const float*)d_in[6];
    const float* b_out  = (const float*)d_in[7];

    float* out = (float*)d_out;
    float* h1  = out + ((size_t)out_size - (size_t)BATCH * HID);

    float* gh;   cudaGetSymbolAddress((void**)&gh,  g_gh);
    float* gi;   cudaGetSymbolAddress((void**)&gi,  g_gi);
    __half* woh; cudaGetSymbolAddress((void**)&woh, g_woh);
    __half* whh; cudaGetSymbolAddress((void**)&whh, g_whh);
    __half* hih; cudaGetSymbolAddress((void**)&hih, g_hidh);
    __half* h1h; cudaGetSymbolAddress((void**)&h1h, g_h1h);

    static cudaStream_t sA = nullptr, sB = nullptr;
    static cudaEvent_t ev0 = nullptr, evA = nullptr, evB = nullptr;
    if (!sA) {
        cudaFuncSetAttribute(gemm_k1,  cudaFuncAttributeMaxDynamicSharedMemorySize, SMEM1);
        cudaFuncSetAttribute(gemm_out, cudaFuncAttributeMaxDynamicSharedMemorySize, SMEM3);
        cudaStreamCreateWithFlags(&sA, cudaStreamNonBlocking);
        cudaStreamCreateWithFlags(&sB, cudaStreamNonBlocking);
        cudaEventCreateWithFlags(&ev0, cudaEventDisableTiming);
        cudaEventCreateWithFlags(&evA, cudaEventDisableTiming);
        cudaEventCreateWithFlags(&evB, cudaEventDisableTiming);
    }

    // fork
    cudaEventRecord(ev0, (cudaStream_t)0);
    cudaStreamWaitEvent(sA, ev0, 0);
    cudaStreamWaitEvent(sB, ev0, 0);

    // stream A: w_out f32 -> f16 (hidden under pre-chain)
    {
        int n4 = (VOCAB * HID) / 4;
        convk<<<(n4 + 255) / 256, 256, 0, sA>>>((const float4*)w_out, (__half2*)woh, n4);
    }
    cudaEventRecord(evA, sA);

    // stream B: w_ih gather (parallel with convsmall + K1)
    gather_gi<<<(BATCH * G3H) / 256, 256, 0, sB>>>(ids, w_ih, b_ih, gi);
    cudaEventRecord(evB, sB);

    // main: small convs -> K1
    convsmall<<<(CONV1_N4 + CONV2_N4 + 255) / 256, 256>>>(
        (const float4*)w_hh, (__half2*)whh,
        (const float4*)hidden, (__half2*)hih);
    gemm_k1<<<dim3(BATCH / TM1, G3H / TN1), 256, SMEM1>>>(hih, whh, gh);

    // join gather, combine
    cudaStreamWaitEvent((cudaStream_t)0, evB, 0);
    gru_comb<<<BATCH, HID>>>(gi, gh, b_hh, hidden, h1, h1h);

    // join conversion, big GEMM
    cudaStreamWaitEvent((cudaStream_t)0, evA, 0);
    gemm_out<<<dim3(BATCH / TM3, GRIDY3), 256, SMEM3>>>(h1h, woh, b_out, out);
}